// round 15
// baseline (speedup 1.0000x reference)
#include <cuda_runtime.h>
#include <cuda_fp16.h>
#include <cstdint>

#define SS 160
#define LL 128
#define DD 256
#define KK 16
#define BB 2048

#define THREADS 256
#define ROWS_PER_WARP 16
#define B_PER_BLOCK (8 * ROWS_PER_WARP)          // 128
#define NBLOCKS (LL * (BB / B_PER_BLOCK))        // 2048

// K1 block ranges: meta first (starts DRAM stream ASAP)
#define NB_META  (BB / 8)          // 256 (8 b-rows per block, 4 per thread)
#define NB_TBL   128
#define NB_COMBO (LL * 8)          // 1024
#define NB_STATS 256               // 65536 patterns / 256

// three split tables: 6+5+5 bits, 64 KB total fp16 -> L1-resident
__device__ __half2  g_T0h[64 * (DD / 2)];
__device__ __half2  g_T1h[32 * (DD / 2)];
__device__ __half2  g_T2h[32 * (DD / 2)];
__device__ __half2  g_comboh[LL * 8 * (DD / 2)];
__device__ float    g_S[64], g_Q[64];
__device__ float    g_D[6 * 256];
__device__ float2   g_stats[65536];              // (rs, -mu*rs) per pattern
__device__ unsigned g_meta[BB * LL];             // pat | a4s<<16 | valid<<31

__device__ __forceinline__ void nib_entry(const float* __restrict__ mlp_w,
                                          const float* __restrict__ mlp_b,
                                          int i, int q, int d, float v[8])
{
#pragma unroll
    for (int x = 0; x < 8; x++) v[x] = (i == 0) ? mlp_b[d + x] : 0.0f;
#pragma unroll
    for (int k = 0; k < 4; k++)
        if ((q >> k) & 1) {
            const float* w = mlp_w + (i * 4 + k) * DD + d;
#pragma unroll
            for (int x = 0; x < 8; x++) v[x] += w[x];
        }
}

__device__ __forceinline__ unsigned pat16(float4 m0, float4 m1, float4 m2, float4 m3)
{
    unsigned pat = 0;
    pat |= (m0.x != 0.f) ? 1u       : 0u;
    pat |= (m0.y != 0.f) ? 1u <<  1 : 0u;
    pat |= (m0.z != 0.f) ? 1u <<  2 : 0u;
    pat |= (m0.w != 0.f) ? 1u <<  3 : 0u;
    pat |= (m1.x != 0.f) ? 1u <<  4 : 0u;
    pat |= (m1.y != 0.f) ? 1u <<  5 : 0u;
    pat |= (m1.z != 0.f) ? 1u <<  6 : 0u;
    pat |= (m1.w != 0.f) ? 1u <<  7 : 0u;
    pat |= (m2.x != 0.f) ? 1u <<  8 : 0u;
    pat |= (m2.y != 0.f) ? 1u <<  9 : 0u;
    pat |= (m2.z != 0.f) ? 1u << 10 : 0u;
    pat |= (m2.w != 0.f) ? 1u << 11 : 0u;
    pat |= (m3.x != 0.f) ? 1u << 12 : 0u;
    pat |= (m3.y != 0.f) ? 1u << 13 : 0u;
    pat |= (m3.z != 0.f) ? 1u << 14 : 0u;
    pat |= (m3.w != 0.f) ? 1u << 15 : 0u;
    return pat;
}

// ---------- K0: S/Q/D tables (tiny; unblocks the stats blocks of K1) ----------
__global__ void precompute0(const float* __restrict__ mlp_w,
                            const float* __restrict__ mlp_b)
{
    const int lane = threadIdx.x & 31;
    const int work = blockIdx.x * 8 + (threadIdx.x >> 5);   // 0..1599
    const int d    = lane * 8;

    if (work < 1536) {
        const int pair = work >> 8;
        const int e    = work & 255;
        const int qi   = e >> 4, qj = e & 15;
        const int pi[6] = {0, 0, 0, 1, 1, 2};
        const int pj[6] = {1, 2, 3, 2, 3, 3};
        float vi[8], vj[8];
        nib_entry(mlp_w, mlp_b, pi[pair], qi, d, vi);
        nib_entry(mlp_w, mlp_b, pj[pair], qj, d, vj);
        float acc = 0.f;
#pragma unroll
        for (int x = 0; x < 8; x++) acc = fmaf(vi[x], vj[x], acc);
#pragma unroll
        for (int o = 16; o > 0; o >>= 1)
            acc += __shfl_xor_sync(0xffffffffu, acc, o);
        if (lane == 0) g_D[pair * 256 + e] = acc;
    } else {
        const int s = work - 1536;
        float v[8];
        nib_entry(mlp_w, mlp_b, s >> 4, s & 15, d, v);
        float sum = 0.f, sq = 0.f;
#pragma unroll
        for (int x = 0; x < 8; x++) { sum += v[x]; sq = fmaf(v[x], v[x], sq); }
#pragma unroll
        for (int o = 16; o > 0; o >>= 1) {
            sum += __shfl_xor_sync(0xffffffffu, sum, o);
            sq  += __shfl_xor_sync(0xffffffffu, sq,  o);
        }
        if (lane == 0) { g_S[s] = sum; g_Q[s] = sq; }
    }
}

// ---------- K1: meta (4 rows/thread) + split tables + combo + stats ----------
__global__ void precompute1(const float* __restrict__ mlp_w,
                            const float* __restrict__ mlp_b,
                            const float* __restrict__ actor_w,
                            const float* __restrict__ street_w,
                            const float* __restrict__ pos_w,
                            const int*   __restrict__ token_ids,
                            const int*   __restrict__ actors,
                            const int*   __restrict__ streets,
                            const float* __restrict__ masks)
{
    const int tid = threadIdx.x;
    const int bid = blockIdx.x;
    __shared__ float buf[DD];

    if (bid < NB_META) {
        // metadata: block covers 8 b-rows; thread handles 4 rows at column l
        const int bBase = bid * 8 + (tid >> 7) * 4;
        const int l     = tid & 127;

        float4 m[4][4];
        int tok[4], act[4], str[4];
#pragma unroll
        for (int r = 0; r < 4; r++) {
            const long idc = (long)(bBase + r) * SS + l;
            const float4* mp = (const float4*)(masks + idc * KK);
            m[r][0] = __ldg(mp + 0);
            m[r][1] = __ldg(mp + 1);
            m[r][2] = __ldg(mp + 2);
            m[r][3] = __ldg(mp + 3);
            tok[r] = __ldg(token_ids + idc);
            act[r] = __ldg(actors    + idc);
            str[r] = __ldg(streets   + idc);
        }
#pragma unroll
        for (int r = 0; r < 4; r++) {
            unsigned mm = pat16(m[r][0], m[r][1], m[r][2], m[r][3])
                        | ((unsigned)(act[r] * 4 + str[r]) << 16);
            if (tok[r] >= 0) mm |= 1u << 31;
            g_meta[(bBase + r) * LL + l] = mm;
        }
    } else if (bid < NB_META + NB_TBL) {
        // split tables fp16
        const int tb = bid - NB_META;
        const int d  = tid;
        float acc;
        __half2* dst;
        if (tb < 64) {
            const int q = tb;
            acc = mlp_b[d];
#pragma unroll
            for (int k = 0; k < 6; k++)
                if ((q >> k) & 1) acc += mlp_w[k * DD + d];
            dst = g_T0h + tb * (DD / 2);
        } else if (tb < 96) {
            const int q = tb - 64;
            acc = 0.0f;
#pragma unroll
            for (int k = 0; k < 5; k++)
                if ((q >> k) & 1) acc += mlp_w[(6 + k) * DD + d];
            dst = g_T1h + (tb - 64) * (DD / 2);
        } else {
            const int q = tb - 96;
            acc = 0.0f;
#pragma unroll
            for (int k = 0; k < 5; k++)
                if ((q >> k) & 1) acc += mlp_w[(11 + k) * DD + d];
            dst = g_T2h + (tb - 96) * (DD / 2);
        }
        buf[d] = acc;
        __syncthreads();
        if (d < DD / 2)
            dst[d] = __float22half2_rn(make_float2(buf[d * 2], buf[d * 2 + 1]));
    } else if (bid < NB_META + NB_TBL + NB_COMBO) {
        // combo fp16
        const int cb = bid - (NB_META + NB_TBL);
        const int c  = cb & 7;
        const int l  = cb >> 3;
        const int d  = tid;
        buf[d] = actor_w[(c >> 2) * DD + d] + street_w[(c & 3) * DD + d]
               + pos_w[l * DD + d];
        __syncthreads();
        if (d < DD / 2)
            g_comboh[cb * (DD / 2) + d] =
                __float22half2_rn(make_float2(buf[d * 2], buf[d * 2 + 1]));
    } else {
        // stats table: needs S/Q/D from K0 (previous launch)
        const int p  = (bid - (NB_META + NB_TBL + NB_COMBO)) * 256 + tid;
        const int q0 = p & 15, q1 = (p >> 4) & 15, q2 = (p >> 8) & 15, q3 = p >> 12;
        const float sum = g_S[q0] + g_S[16 + q1] + g_S[32 + q2] + g_S[48 + q3];
        const float sq  = g_Q[q0] + g_Q[16 + q1] + g_Q[32 + q2] + g_Q[48 + q3]
            + 2.0f * ( g_D[0*256 + q0*16 + q1] + g_D[1*256 + q0*16 + q2]
                     + g_D[2*256 + q0*16 + q3] + g_D[3*256 + q1*16 + q2]
                     + g_D[4*256 + q1*16 + q3] + g_D[5*256 + q2*16 + q3]);
        const float mu  = sum * (1.0f / DD);
        const float var = fmaf(-mu, mu, sq * (1.0f / DD));
        const float rs  = rsqrtf(var + 1e-5f);
        float2 r; r.x = rs; r.y = -mu * rs;
        g_stats[p] = r;
    }
}

// ---------- 32-byte streaming store ----------
__device__ __forceinline__ void stg_cs32(float* p, float4 a, float4 b) {
    unsigned long long r0, r1, r2, r3;
    asm("mov.b64 %0, {%1, %2};" : "=l"(r0) : "f"(a.x), "f"(a.y));
    asm("mov.b64 %0, {%1, %2};" : "=l"(r1) : "f"(a.z), "f"(a.w));
    asm("mov.b64 %0, {%1, %2};" : "=l"(r2) : "f"(b.x), "f"(b.y));
    asm("mov.b64 %0, {%1, %2};" : "=l"(r3) : "f"(b.z), "f"(b.w));
    asm volatile("st.global.cs.v4.b64 [%0], {%1,%2,%3,%4};"
                 :: "l"(p), "l"(r0), "l"(r1), "l"(r2), "l"(r3) : "memory");
}

// ---------- main kernel ----------
__global__ __launch_bounds__(THREADS, 6)
void action_emb_kernel(const float* __restrict__ ln_g,
                       const float* __restrict__ ln_b,
                       float*       __restrict__ out)
{
    const int tid  = threadIdx.x;
    const int lane = tid & 31;
    const int warp = tid >> 5;
    const int d0   = lane * 8;

    const int l     = blockIdx.x & (LL - 1);
    const int chunk = blockIdx.x >> 7;
    const int b0    = chunk * B_PER_BLOCK + warp * ROWS_PER_WARP;

    const float4 gA = *(const float4*)(ln_g + d0);
    const float4 gB = *(const float4*)(ln_g + d0 + 4);
    const float4 bA = *(const float4*)(ln_b + d0);
    const float4 bB = *(const float4*)(ln_b + d0 + 4);

    const __half2* comboL = g_comboh + (l * 8) * (DD / 2) + lane * 4;

    // lanes 0-15 own one row each: meta + stats
    unsigned m32 = 0;
    float2   st16 = make_float2(0.f, 0.f);
    if (lane < ROWS_PER_WARP) {
        m32  = g_meta[(b0 + lane) * LL + l];
        st16 = __ldg(&g_stats[m32 & 0xFFFFu]);
    }

    int oofs = (b0 * LL + l) * DD + d0;
    const int OSTEP = LL * DD;

#pragma unroll
    for (int it = 0; it < ROWS_PER_WARP; it++) {
        const unsigned mc   = __shfl_sync(0xffffffffu, m32, it);
        const float    rs   = __shfl_sync(0xffffffffu, st16.x, it);
        const float    nmrs = __shfl_sync(0xffffffffu, st16.y, it);

        const unsigned q0 =  mc        & 63u;
        const unsigned q1 = (mc >>  6) & 31u;
        const unsigned q2 = (mc >> 11) & 31u;

        const uint4 t0v = __ldg((const uint4*)(g_T0h + q0 * (DD/2) + lane * 4));
        const uint4 t1v = __ldg((const uint4*)(g_T1h + q1 * (DD/2) + lane * 4));
        const uint4 t2v = __ldg((const uint4*)(g_T2h + q2 * (DD/2) + lane * 4));
        const uint4 cv  = __ldg((const uint4*)(comboL + ((mc >> 16) & 7u) * (DD/2)));

        const __half2 s0 = __hadd2(__hadd2(*(const __half2*)&t0v.x,
                                           *(const __half2*)&t1v.x),
                                   *(const __half2*)&t2v.x);
        const __half2 s1 = __hadd2(__hadd2(*(const __half2*)&t0v.y,
                                           *(const __half2*)&t1v.y),
                                   *(const __half2*)&t2v.y);
        const __half2 s2 = __hadd2(__hadd2(*(const __half2*)&t0v.z,
                                           *(const __half2*)&t1v.z),
                                   *(const __half2*)&t2v.z);
        const __half2 s3 = __hadd2(__hadd2(*(const __half2*)&t0v.w,
                                           *(const __half2*)&t1v.w),
                                   *(const __half2*)&t2v.w);

        const float2 h0 = __half22float2(s0);
        const float2 h1 = __half22float2(s1);
        const float2 h2 = __half22float2(s2);
        const float2 h3 = __half22float2(s3);

        const float2 c0 = __half22float2(*(const __half2*)&cv.x);
        const float2 c1 = __half22float2(*(const __half2*)&cv.y);
        const float2 c2 = __half22float2(*(const __half2*)&cv.z);
        const float2 c3 = __half22float2(*(const __half2*)&cv.w);

        float4 oA, oB;
        oA.x = fmaxf(fmaf(fmaf(h0.x, rs, nmrs), gA.x, bA.x), 0.0f) + c0.x;
        oA.y = fmaxf(fmaf(fmaf(h0.y, rs, nmrs), gA.y, bA.y), 0.0f) + c0.y;
        oA.z = fmaxf(fmaf(fmaf(h1.x, rs, nmrs), gA.z, bA.z), 0.0f) + c1.x;
        oA.w = fmaxf(fmaf(fmaf(h1.y, rs, nmrs), gA.w, bA.w), 0.0f) + c1.y;
        oB.x = fmaxf(fmaf(fmaf(h2.x, rs, nmrs), gB.x, bB.x), 0.0f) + c2.x;
        oB.y = fmaxf(fmaf(fmaf(h2.y, rs, nmrs), gB.y, bB.y), 0.0f) + c2.y;
        oB.z = fmaxf(fmaf(fmaf(h3.x, rs, nmrs), gB.z, bB.z), 0.0f) + c3.x;
        oB.w = fmaxf(fmaf(fmaf(h3.y, rs, nmrs), gB.w, bB.w), 0.0f) + c3.y;

        if (!(mc >> 31)) {
            oA.x = oA.y = oA.z = oA.w = 0.0f;
            oB.x = oB.y = oB.z = oB.w = 0.0f;
        }

        stg_cs32(out + oofs, oA, oB);
        oofs += OSTEP;
    }
}

extern "C" void kernel_launch(void* const* d_in, const int* in_sizes, int n_in,
                              void* d_out, int out_size)
{
    const int*   token_ids = (const int*)  d_in[0];
    const int*   actors    = (const int*)  d_in[1];
    const int*   streets   = (const int*)  d_in[2];
    const float* masks     = (const float*)d_in[3];
    const float* actor_w   = (const float*)d_in[4];
    const float* street_w  = (const float*)d_in[5];
    const float* pos_w     = (const float*)d_in[6];
    const float* mlp_w     = (const float*)d_in[7];
    const float* mlp_b     = (const float*)d_in[8];
    const float* ln_g      = (const float*)d_in[9];
    const float* ln_b      = (const float*)d_in[10];
    float*       out       = (float*)d_out;

    precompute0<<<200, 256>>>(mlp_w, mlp_b);
    precompute1<<<NB_META + NB_TBL + NB_COMBO + NB_STATS, 256>>>(
        mlp_w, mlp_b, actor_w, street_w, pos_w,
        token_ids, actors, streets, masks);
    action_emb_kernel<<<NBLOCKS, THREADS>>>(ln_g, ln_b, out);
}

// round 16
// speedup vs baseline: 1.0485x; 1.0485x over previous
#include <cuda_runtime.h>
#include <cuda_fp16.h>
#include <cstdint>

#define SS 160
#define LL 128
#define DD 256
#define KK 16
#define BB 2048

#define THREADS 256
#define ROWS_PER_WARP 16
#define B_PER_BLOCK (8 * ROWS_PER_WARP)          // 128
#define NBLOCKS (LL * (BB / B_PER_BLOCK))        // 2048

// K1 block ordering: SQD chains first (overlap meta streaming), then meta, tables, combo
#define NB_SQD   200
#define NB_META  (BB / 8)          // 256 (8 b-rows per block, 4 per thread)
#define NB_TBL   128
#define NB_COMBO (LL * 8)          // 1024

__device__ __half2  g_T0h[64 * (DD / 2)];
__device__ __half2  g_T1h[32 * (DD / 2)];
__device__ __half2  g_T2h[32 * (DD / 2)];
__device__ __half2  g_comboh[LL * 8 * (DD / 2)];
__device__ float    g_S[64], g_Q[64];
__device__ float    g_D[6 * 256];
__device__ float2   g_stats[65536];              // (rs, -mu*rs) per pattern
__device__ unsigned g_meta[BB * LL];             // pat | a4s<<16 | valid<<31

__device__ __forceinline__ void nib_entry(const float* __restrict__ mlp_w,
                                          const float* __restrict__ mlp_b,
                                          int i, int q, int d, float v[8])
{
#pragma unroll
    for (int x = 0; x < 8; x++) v[x] = (i == 0) ? mlp_b[d + x] : 0.0f;
#pragma unroll
    for (int k = 0; k < 4; k++)
        if ((q >> k) & 1) {
            const float* w = mlp_w + (i * 4 + k) * DD + d;
#pragma unroll
            for (int x = 0; x < 8; x++) v[x] += w[x];
        }
}

__device__ __forceinline__ unsigned pat16(float4 m0, float4 m1, float4 m2, float4 m3)
{
    unsigned pat = 0;
    pat |= (m0.x != 0.f) ? 1u       : 0u;
    pat |= (m0.y != 0.f) ? 1u <<  1 : 0u;
    pat |= (m0.z != 0.f) ? 1u <<  2 : 0u;
    pat |= (m0.w != 0.f) ? 1u <<  3 : 0u;
    pat |= (m1.x != 0.f) ? 1u <<  4 : 0u;
    pat |= (m1.y != 0.f) ? 1u <<  5 : 0u;
    pat |= (m1.z != 0.f) ? 1u <<  6 : 0u;
    pat |= (m1.w != 0.f) ? 1u <<  7 : 0u;
    pat |= (m2.x != 0.f) ? 1u <<  8 : 0u;
    pat |= (m2.y != 0.f) ? 1u <<  9 : 0u;
    pat |= (m2.z != 0.f) ? 1u << 10 : 0u;
    pat |= (m2.w != 0.f) ? 1u << 11 : 0u;
    pat |= (m3.x != 0.f) ? 1u << 12 : 0u;
    pat |= (m3.y != 0.f) ? 1u << 13 : 0u;
    pat |= (m3.z != 0.f) ? 1u << 14 : 0u;
    pat |= (m3.w != 0.f) ? 1u << 15 : 0u;
    return pat;
}

// ---------- K1: SQD + meta(4 rows/thread) + split tables + combo ----------
__global__ void precompute1(const float* __restrict__ mlp_w,
                            const float* __restrict__ mlp_b,
                            const float* __restrict__ actor_w,
                            const float* __restrict__ street_w,
                            const float* __restrict__ pos_w,
                            const int*   __restrict__ token_ids,
                            const int*   __restrict__ actors,
                            const int*   __restrict__ streets,
                            const float* __restrict__ masks)
{
    const int tid = threadIdx.x;
    const int bid = blockIdx.x;
    __shared__ float buf[DD];

    if (bid < NB_SQD) {
        // S/Q/D: one work item per warp — long chains start first
        const int lane = tid & 31;
        const int work = bid * 8 + (tid >> 5);   // 0..1599
        const int d    = lane * 8;

        if (work < 1536) {
            const int pair = work >> 8;
            const int e    = work & 255;
            const int qi   = e >> 4, qj = e & 15;
            const int pi[6] = {0, 0, 0, 1, 1, 2};
            const int pj[6] = {1, 2, 3, 2, 3, 3};
            float vi[8], vj[8];
            nib_entry(mlp_w, mlp_b, pi[pair], qi, d, vi);
            nib_entry(mlp_w, mlp_b, pj[pair], qj, d, vj);
            float acc = 0.f;
#pragma unroll
            for (int x = 0; x < 8; x++) acc = fmaf(vi[x], vj[x], acc);
#pragma unroll
            for (int o = 16; o > 0; o >>= 1)
                acc += __shfl_xor_sync(0xffffffffu, acc, o);
            if (lane == 0) g_D[pair * 256 + e] = acc;
        } else {
            const int s = work - 1536;
            float v[8];
            nib_entry(mlp_w, mlp_b, s >> 4, s & 15, d, v);
            float sum = 0.f, sq = 0.f;
#pragma unroll
            for (int x = 0; x < 8; x++) { sum += v[x]; sq = fmaf(v[x], v[x], sq); }
#pragma unroll
            for (int o = 16; o > 0; o >>= 1) {
                sum += __shfl_xor_sync(0xffffffffu, sum, o);
                sq  += __shfl_xor_sync(0xffffffffu, sq,  o);
            }
            if (lane == 0) { g_S[s] = sum; g_Q[s] = sq; }
        }
    } else if (bid < NB_SQD + NB_META) {
        // metadata: block covers 8 b-rows; thread handles 4 rows at column l
        const int bBase = (bid - NB_SQD) * 8 + (tid >> 7) * 4;
        const int l     = tid & 127;

        float4 m[4][4];
        int tok[4], act[4], str[4];
#pragma unroll
        for (int r = 0; r < 4; r++) {
            const long idc = (long)(bBase + r) * SS + l;
            const float4* mp = (const float4*)(masks + idc * KK);
            m[r][0] = __ldg(mp + 0);
            m[r][1] = __ldg(mp + 1);
            m[r][2] = __ldg(mp + 2);
            m[r][3] = __ldg(mp + 3);
            tok[r] = __ldg(token_ids + idc);
            act[r] = __ldg(actors    + idc);
            str[r] = __ldg(streets   + idc);
        }
#pragma unroll
        for (int r = 0; r < 4; r++) {
            unsigned mm = pat16(m[r][0], m[r][1], m[r][2], m[r][3])
                        | ((unsigned)(act[r] * 4 + str[r]) << 16);
            if (tok[r] >= 0) mm |= 1u << 31;
            g_meta[(bBase + r) * LL + l] = mm;
        }
    } else if (bid < NB_SQD + NB_META + NB_TBL) {
        // split tables fp16
        const int tb = bid - (NB_SQD + NB_META);
        const int d  = tid;
        float acc;
        __half2* dst;
        if (tb < 64) {
            const int q = tb;
            acc = mlp_b[d];
#pragma unroll
            for (int k = 0; k < 6; k++)
                if ((q >> k) & 1) acc += mlp_w[k * DD + d];
            dst = g_T0h + tb * (DD / 2);
        } else if (tb < 96) {
            const int q = tb - 64;
            acc = 0.0f;
#pragma unroll
            for (int k = 0; k < 5; k++)
                if ((q >> k) & 1) acc += mlp_w[(6 + k) * DD + d];
            dst = g_T1h + (tb - 64) * (DD / 2);
        } else {
            const int q = tb - 96;
            acc = 0.0f;
#pragma unroll
            for (int k = 0; k < 5; k++)
                if ((q >> k) & 1) acc += mlp_w[(11 + k) * DD + d];
            dst = g_T2h + (tb - 96) * (DD / 2);
        }
        buf[d] = acc;
        __syncthreads();
        if (d < DD / 2)
            dst[d] = __float22half2_rn(make_float2(buf[d * 2], buf[d * 2 + 1]));
    } else {
        // combo fp16
        const int cb = bid - (NB_SQD + NB_META + NB_TBL);
        const int c  = cb & 7;
        const int l  = cb >> 3;
        const int d  = tid;
        buf[d] = actor_w[(c >> 2) * DD + d] + street_w[(c & 3) * DD + d]
               + pos_w[l * DD + d];
        __syncthreads();
        if (d < DD / 2)
            g_comboh[cb * (DD / 2) + d] =
                __float22half2_rn(make_float2(buf[d * 2], buf[d * 2 + 1]));
    }
}

// ---------- K2: LN stats per pattern -> (rs, -mu*rs) ----------
__global__ void precompute3()
{
    const int p  = blockIdx.x * 256 + threadIdx.x;
    const int q0 = p & 15, q1 = (p >> 4) & 15, q2 = (p >> 8) & 15, q3 = p >> 12;
    const float sum = g_S[q0] + g_S[16 + q1] + g_S[32 + q2] + g_S[48 + q3];
    const float sq  = g_Q[q0] + g_Q[16 + q1] + g_Q[32 + q2] + g_Q[48 + q3]
        + 2.0f * ( g_D[0*256 + q0*16 + q1] + g_D[1*256 + q0*16 + q2]
                 + g_D[2*256 + q0*16 + q3] + g_D[3*256 + q1*16 + q2]
                 + g_D[4*256 + q1*16 + q3] + g_D[5*256 + q2*16 + q3]);
    const float mu  = sum * (1.0f / DD);
    const float var = fmaf(-mu, mu, sq * (1.0f / DD));
    const float rs  = rsqrtf(var + 1e-5f);
    float2 r; r.x = rs; r.y = -mu * rs;
    g_stats[p] = r;
}

// ---------- 32-byte streaming store ----------
__device__ __forceinline__ void stg_cs32(float* p, float4 a, float4 b) {
    unsigned long long r0, r1, r2, r3;
    asm("mov.b64 %0, {%1, %2};" : "=l"(r0) : "f"(a.x), "f"(a.y));
    asm("mov.b64 %0, {%1, %2};" : "=l"(r1) : "f"(a.z), "f"(a.w));
    asm("mov.b64 %0, {%1, %2};" : "=l"(r2) : "f"(b.x), "f"(b.y));
    asm("mov.b64 %0, {%1, %2};" : "=l"(r3) : "f"(b.z), "f"(b.w));
    asm volatile("st.global.cs.v4.b64 [%0], {%1,%2,%3,%4};"
                 :: "l"(p), "l"(r0), "l"(r1), "l"(r2), "l"(r3) : "memory");
}

// ---------- main kernel ----------
__global__ __launch_bounds__(THREADS, 6)
void action_emb_kernel(const float* __restrict__ ln_g,
                       const float* __restrict__ ln_b,
                       float*       __restrict__ out)
{
    const int tid  = threadIdx.x;
    const int lane = tid & 31;
    const int warp = tid >> 5;
    const int d0   = lane * 8;

    const int l     = blockIdx.x & (LL - 1);
    const int chunk = blockIdx.x >> 7;
    const int b0    = chunk * B_PER_BLOCK + warp * ROWS_PER_WARP;

    const float4 gA = *(const float4*)(ln_g + d0);
    const float4 gB = *(const float4*)(ln_g + d0 + 4);
    const float4 bA = *(const float4*)(ln_b + d0);
    const float4 bB = *(const float4*)(ln_b + d0 + 4);

    const __half2* comboL = g_comboh + (l * 8) * (DD / 2) + lane * 4;

    // lanes 0-15 own one row each: meta + stats
    unsigned m32 = 0;
    float2   st16 = make_float2(0.f, 0.f);
    if (lane < ROWS_PER_WARP) {
        m32  = g_meta[(b0 + lane) * LL + l];
        st16 = __ldg(&g_stats[m32 & 0xFFFFu]);
    }

    int oofs = (b0 * LL + l) * DD + d0;
    const int OSTEP = LL * DD;

#pragma unroll
    for (int it = 0; it < ROWS_PER_WARP; it++) {
        const unsigned mc   = __shfl_sync(0xffffffffu, m32, it);
        const float    rs   = __shfl_sync(0xffffffffu, st16.x, it);
        const float    nmrs = __shfl_sync(0xffffffffu, st16.y, it);

        const unsigned q0 =  mc        & 63u;
        const unsigned q1 = (mc >>  6) & 31u;
        const unsigned q2 = (mc >> 11) & 31u;

        const uint4 t0v = __ldg((const uint4*)(g_T0h + q0 * (DD/2) + lane * 4));
        const uint4 t1v = __ldg((const uint4*)(g_T1h + q1 * (DD/2) + lane * 4));
        const uint4 t2v = __ldg((const uint4*)(g_T2h + q2 * (DD/2) + lane * 4));
        const uint4 cv  = __ldg((const uint4*)(comboL + ((mc >> 16) & 7u) * (DD/2)));

        const __half2 s0 = __hadd2(__hadd2(*(const __half2*)&t0v.x,
                                           *(const __half2*)&t1v.x),
                                   *(const __half2*)&t2v.x);
        const __half2 s1 = __hadd2(__hadd2(*(const __half2*)&t0v.y,
                                           *(const __half2*)&t1v.y),
                                   *(const __half2*)&t2v.y);
        const __half2 s2 = __hadd2(__hadd2(*(const __half2*)&t0v.z,
                                           *(const __half2*)&t1v.z),
                                   *(const __half2*)&t2v.z);
        const __half2 s3 = __hadd2(__hadd2(*(const __half2*)&t0v.w,
                                           *(const __half2*)&t1v.w),
                                   *(const __half2*)&t2v.w);

        const float2 h0 = __half22float2(s0);
        const float2 h1 = __half22float2(s1);
        const float2 h2 = __half22float2(s2);
        const float2 h3 = __half22float2(s3);

        const float2 c0 = __half22float2(*(const __half2*)&cv.x);
        const float2 c1 = __half22float2(*(const __half2*)&cv.y);
        const float2 c2 = __half22float2(*(const __half2*)&cv.z);
        const float2 c3 = __half22float2(*(const __half2*)&cv.w);

        float4 oA, oB;
        oA.x = fmaxf(fmaf(fmaf(h0.x, rs, nmrs), gA.x, bA.x), 0.0f) + c0.x;
        oA.y = fmaxf(fmaf(fmaf(h0.y, rs, nmrs), gA.y, bA.y), 0.0f) + c0.y;
        oA.z = fmaxf(fmaf(fmaf(h1.x, rs, nmrs), gA.z, bA.z), 0.0f) + c1.x;
        oA.w = fmaxf(fmaf(fmaf(h1.y, rs, nmrs), gA.w, bA.w), 0.0f) + c1.y;
        oB.x = fmaxf(fmaf(fmaf(h2.x, rs, nmrs), gB.x, bB.x), 0.0f) + c2.x;
        oB.y = fmaxf(fmaf(fmaf(h2.y, rs, nmrs), gB.y, bB.y), 0.0f) + c2.y;
        oB.z = fmaxf(fmaf(fmaf(h3.x, rs, nmrs), gB.z, bB.z), 0.0f) + c3.x;
        oB.w = fmaxf(fmaf(fmaf(h3.y, rs, nmrs), gB.w, bB.w), 0.0f) + c3.y;

        if (!(mc >> 31)) {
            oA.x = oA.y = oA.z = oA.w = 0.0f;
            oB.x = oB.y = oB.z = oB.w = 0.0f;
        }

        stg_cs32(out + oofs, oA, oB);
        oofs += OSTEP;
    }
}

extern "C" void kernel_launch(void* const* d_in, const int* in_sizes, int n_in,
                              void* d_out, int out_size)
{
    const int*   token_ids = (const int*)  d_in[0];
    const int*   actors    = (const int*)  d_in[1];
    const int*   streets   = (const int*)  d_in[2];
    const float* masks     = (const float*)d_in[3];
    const float* actor_w   = (const float*)d_in[4];
    const float* street_w  = (const float*)d_in[5];
    const float* pos_w     = (const float*)d_in[6];
    const float* mlp_w     = (const float*)d_in[7];
    const float* mlp_b     = (const float*)d_in[8];
    const float* ln_g      = (const float*)d_in[9];
    const float* ln_b      = (const float*)d_in[10];
    float*       out       = (float*)d_out;

    precompute1<<<NB_SQD + NB_META + NB_TBL + NB_COMBO, 256>>>(
        mlp_w, mlp_b, actor_w, street_w, pos_w,
        token_ids, actors, streets, masks);
    precompute3<<<256, 256>>>();
    action_emb_kernel<<<NBLOCKS, THREADS>>>(ln_g, ln_b, out);
}

// round 17
// speedup vs baseline: 1.0491x; 1.0006x over previous
#include <cuda_runtime.h>
#include <cuda_fp16.h>
#include <cstdint>

#define SS 160
#define LL 128
#define DD 256
#define KK 16
#define BB 2048

#define THREADS 256
#define ROWS_PER_WARP 16
#define B_PER_BLOCK (8 * ROWS_PER_WARP)          // 128
#define NBLOCKS (LL * (BB / B_PER_BLOCK))        // 2048

// K1 block ordering: META first (span-defining DRAM stream), then SQD, tables, combo
#define NB_META  (BB / 8)          // 256 (8 b-rows per block, 4 per thread)
#define NB_SQD   200
#define NB_TBL   128
#define NB_COMBO (LL * 2)          // 256 (4 combos per block)

__device__ __half2  g_T0h[64 * (DD / 2)];
__device__ __half2  g_T1h[32 * (DD / 2)];
__device__ __half2  g_T2h[32 * (DD / 2)];
__device__ __half2  g_comboh[LL * 8 * (DD / 2)];
__device__ float    g_S[64], g_Q[64];
__device__ float    g_D[6 * 256];
__device__ float2   g_stats[65536];              // (rs, -mu*rs) per pattern
__device__ unsigned g_meta[BB * LL];             // pat | a4s<<16 | valid<<31

__device__ __forceinline__ void nib_entry(const float* __restrict__ mlp_w,
                                          const float* __restrict__ mlp_b,
                                          int i, int q, int d, float v[8])
{
#pragma unroll
    for (int x = 0; x < 8; x++) v[x] = (i == 0) ? mlp_b[d + x] : 0.0f;
#pragma unroll
    for (int k = 0; k < 4; k++)
        if ((q >> k) & 1) {
            const float* w = mlp_w + (i * 4 + k) * DD + d;
#pragma unroll
            for (int x = 0; x < 8; x++) v[x] += w[x];
        }
}

__device__ __forceinline__ unsigned pat16(float4 m0, float4 m1, float4 m2, float4 m3)
{
    unsigned pat = 0;
    pat |= (m0.x != 0.f) ? 1u       : 0u;
    pat |= (m0.y != 0.f) ? 1u <<  1 : 0u;
    pat |= (m0.z != 0.f) ? 1u <<  2 : 0u;
    pat |= (m0.w != 0.f) ? 1u <<  3 : 0u;
    pat |= (m1.x != 0.f) ? 1u <<  4 : 0u;
    pat |= (m1.y != 0.f) ? 1u <<  5 : 0u;
    pat |= (m1.z != 0.f) ? 1u <<  6 : 0u;
    pat |= (m1.w != 0.f) ? 1u <<  7 : 0u;
    pat |= (m2.x != 0.f) ? 1u <<  8 : 0u;
    pat |= (m2.y != 0.f) ? 1u <<  9 : 0u;
    pat |= (m2.z != 0.f) ? 1u << 10 : 0u;
    pat |= (m2.w != 0.f) ? 1u << 11 : 0u;
    pat |= (m3.x != 0.f) ? 1u << 12 : 0u;
    pat |= (m3.y != 0.f) ? 1u << 13 : 0u;
    pat |= (m3.z != 0.f) ? 1u << 14 : 0u;
    pat |= (m3.w != 0.f) ? 1u << 15 : 0u;
    return pat;
}

// ---------- K1: meta(4 rows/thread) + SQD + split tables + combo(x4) ----------
__global__ void precompute1(const float* __restrict__ mlp_w,
                            const float* __restrict__ mlp_b,
                            const float* __restrict__ actor_w,
                            const float* __restrict__ street_w,
                            const float* __restrict__ pos_w,
                            const int*   __restrict__ token_ids,
                            const int*   __restrict__ actors,
                            const int*   __restrict__ streets,
                            const float* __restrict__ masks)
{
    const int tid = threadIdx.x;
    const int bid = blockIdx.x;
    __shared__ float buf[DD];

    if (bid < NB_META) {
        // metadata: block covers 8 b-rows; thread handles 4 rows at column l
        const int bBase = bid * 8 + (tid >> 7) * 4;
        const int l     = tid & 127;

        float4 m[4][4];
        int tok[4], act[4], str[4];
#pragma unroll
        for (int r = 0; r < 4; r++) {
            const long idc = (long)(bBase + r) * SS + l;
            const float4* mp = (const float4*)(masks + idc * KK);
            m[r][0] = __ldg(mp + 0);
            m[r][1] = __ldg(mp + 1);
            m[r][2] = __ldg(mp + 2);
            m[r][3] = __ldg(mp + 3);
            tok[r] = __ldg(token_ids + idc);
            act[r] = __ldg(actors    + idc);
            str[r] = __ldg(streets   + idc);
        }
#pragma unroll
        for (int r = 0; r < 4; r++) {
            unsigned mm = pat16(m[r][0], m[r][1], m[r][2], m[r][3])
                        | ((unsigned)(act[r] * 4 + str[r]) << 16);
            if (tok[r] >= 0) mm |= 1u << 31;
            g_meta[(bBase + r) * LL + l] = mm;
        }
    } else if (bid < NB_META + NB_SQD) {
        // S/Q/D: one work item per warp
        const int lane = tid & 31;
        const int work = (bid - NB_META) * 8 + (tid >> 5);   // 0..1599
        const int d    = lane * 8;

        if (work < 1536) {
            const int pair = work >> 8;
            const int e    = work & 255;
            const int qi   = e >> 4, qj = e & 15;
            const int pi[6] = {0, 0, 0, 1, 1, 2};
            const int pj[6] = {1, 2, 3, 2, 3, 3};
            float vi[8], vj[8];
            nib_entry(mlp_w, mlp_b, pi[pair], qi, d, vi);
            nib_entry(mlp_w, mlp_b, pj[pair], qj, d, vj);
            float acc = 0.f;
#pragma unroll
            for (int x = 0; x < 8; x++) acc = fmaf(vi[x], vj[x], acc);
#pragma unroll
            for (int o = 16; o > 0; o >>= 1)
                acc += __shfl_xor_sync(0xffffffffu, acc, o);
            if (lane == 0) g_D[pair * 256 + e] = acc;
        } else {
            const int s = work - 1536;
            float v[8];
            nib_entry(mlp_w, mlp_b, s >> 4, s & 15, d, v);
            float sum = 0.f, sq = 0.f;
#pragma unroll
            for (int x = 0; x < 8; x++) { sum += v[x]; sq = fmaf(v[x], v[x], sq); }
#pragma unroll
            for (int o = 16; o > 0; o >>= 1) {
                sum += __shfl_xor_sync(0xffffffffu, sum, o);
                sq  += __shfl_xor_sync(0xffffffffu, sq,  o);
            }
            if (lane == 0) { g_S[s] = sum; g_Q[s] = sq; }
        }
    } else if (bid < NB_META + NB_SQD + NB_TBL) {
        // split tables fp16
        const int tb = bid - (NB_META + NB_SQD);
        const int d  = tid;
        float acc;
        __half2* dst;
        if (tb < 64) {
            const int q = tb;
            acc = mlp_b[d];
#pragma unroll
            for (int k = 0; k < 6; k++)
                if ((q >> k) & 1) acc += mlp_w[k * DD + d];
            dst = g_T0h + tb * (DD / 2);
        } else if (tb < 96) {
            const int q = tb - 64;
            acc = 0.0f;
#pragma unroll
            for (int k = 0; k < 5; k++)
                if ((q >> k) & 1) acc += mlp_w[(6 + k) * DD + d];
            dst = g_T1h + (tb - 64) * (DD / 2);
        } else {
            const int q = tb - 96;
            acc = 0.0f;
#pragma unroll
            for (int k = 0; k < 5; k++)
                if ((q >> k) & 1) acc += mlp_w[(11 + k) * DD + d];
            dst = g_T2h + (tb - 96) * (DD / 2);
        }
        buf[d] = acc;
        __syncthreads();
        if (d < DD / 2)
            dst[d] = __float22half2_rn(make_float2(buf[d * 2], buf[d * 2 + 1]));
    } else {
        // combo fp16: block handles one (l, a) pair = 4 combos; 128 active threads
        const int cbBase = (bid - (NB_META + NB_SQD + NB_TBL)) * 4;  // aligned to 4
        const int l      = cbBase >> 3;
        const int a      = (cbBase >> 2) & 1;
        if (tid < DD / 2) {
            const int d2 = tid * 2;
            const float p0 = pos_w[l * DD + d2],     p1 = pos_w[l * DD + d2 + 1];
            const float a0 = actor_w[a * DD + d2],   a1 = actor_w[a * DD + d2 + 1];
            const float base0 = p0 + a0, base1 = p1 + a1;
#pragma unroll
            for (int s = 0; s < 4; s++) {
                const float v0 = base0 + street_w[s * DD + d2];
                const float v1 = base1 + street_w[s * DD + d2 + 1];
                g_comboh[(cbBase + s) * (DD / 2) + tid] =
                    __float22half2_rn(make_float2(v0, v1));
            }
        }
    }
}

// ---------- K2: LN stats per pattern -> (rs, -mu*rs) ----------
__global__ void precompute3()
{
    const int p  = blockIdx.x * 256 + threadIdx.x;
    const int q0 = p & 15, q1 = (p >> 4) & 15, q2 = (p >> 8) & 15, q3 = p >> 12;
    const float sum = g_S[q0] + g_S[16 + q1] + g_S[32 + q2] + g_S[48 + q3];
    const float sq  = g_Q[q0] + g_Q[16 + q1] + g_Q[32 + q2] + g_Q[48 + q3]
        + 2.0f * ( g_D[0*256 + q0*16 + q1] + g_D[1*256 + q0*16 + q2]
                 + g_D[2*256 + q0*16 + q3] + g_D[3*256 + q1*16 + q2]
                 + g_D[4*256 + q1*16 + q3] + g_D[5*256 + q2*16 + q3]);
    const float mu  = sum * (1.0f / DD);
    const float var = fmaf(-mu, mu, sq * (1.0f / DD));
    const float rs  = rsqrtf(var + 1e-5f);
    float2 r; r.x = rs; r.y = -mu * rs;
    g_stats[p] = r;
}

// ---------- 32-byte streaming store ----------
__device__ __forceinline__ void stg_cs32(float* p, float4 a, float4 b) {
    unsigned long long r0, r1, r2, r3;
    asm("mov.b64 %0, {%1, %2};" : "=l"(r0) : "f"(a.x), "f"(a.y));
    asm("mov.b64 %0, {%1, %2};" : "=l"(r1) : "f"(a.z), "f"(a.w));
    asm("mov.b64 %0, {%1, %2};" : "=l"(r2) : "f"(b.x), "f"(b.y));
    asm("mov.b64 %0, {%1, %2};" : "=l"(r3) : "f"(b.z), "f"(b.w));
    asm volatile("st.global.cs.v4.b64 [%0], {%1,%2,%3,%4};"
                 :: "l"(p), "l"(r0), "l"(r1), "l"(r2), "l"(r3) : "memory");
}

// ---------- main kernel ----------
__global__ __launch_bounds__(THREADS, 6)
void action_emb_kernel(const float* __restrict__ ln_g,
                       const float* __restrict__ ln_b,
                       float*       __restrict__ out)
{
    const int tid  = threadIdx.x;
    const int lane = tid & 31;
    const int warp = tid >> 5;
    const int d0   = lane * 8;

    const int l     = blockIdx.x & (LL - 1);
    const int chunk = blockIdx.x >> 7;
    const int b0    = chunk * B_PER_BLOCK + warp * ROWS_PER_WARP;

    const float4 gA = *(const float4*)(ln_g + d0);
    const float4 gB = *(const float4*)(ln_g + d0 + 4);
    const float4 bA = *(const float4*)(ln_b + d0);
    const float4 bB = *(const float4*)(ln_b + d0 + 4);

    const __half2* comboL = g_comboh + (l * 8) * (DD / 2) + lane * 4;

    // lanes 0-15 own one row each: meta + stats
    unsigned m32 = 0;
    float2   st16 = make_float2(0.f, 0.f);
    if (lane < ROWS_PER_WARP) {
        m32  = g_meta[(b0 + lane) * LL + l];
        st16 = __ldg(&g_stats[m32 & 0xFFFFu]);
    }

    int oofs = (b0 * LL + l) * DD + d0;
    const int OSTEP = LL * DD;

#pragma unroll
    for (int it = 0; it < ROWS_PER_WARP; it++) {
        const unsigned mc   = __shfl_sync(0xffffffffu, m32, it);
        const float    rs   = __shfl_sync(0xffffffffu, st16.x, it);
        const float    nmrs = __shfl_sync(0xffffffffu, st16.y, it);

        const unsigned q0 =  mc        & 63u;
        const unsigned q1 = (mc >>  6) & 31u;
        const unsigned q2 = (mc >> 11) & 31u;

        const uint4 t0v = __ldg((const uint4*)(g_T0h + q0 * (DD/2) + lane * 4));
        const uint4 t1v = __ldg((const uint4*)(g_T1h + q1 * (DD/2) + lane * 4));
        const uint4 t2v = __ldg((const uint4*)(g_T2h + q2 * (DD/2) + lane * 4));
        const uint4 cv  = __ldg((const uint4*)(comboL + ((mc >> 16) & 7u) * (DD/2)));

        const __half2 s0 = __hadd2(__hadd2(*(const __half2*)&t0v.x,
                                           *(const __half2*)&t1v.x),
                                   *(const __half2*)&t2v.x);
        const __half2 s1 = __hadd2(__hadd2(*(const __half2*)&t0v.y,
                                           *(const __half2*)&t1v.y),
                                   *(const __half2*)&t2v.y);
        const __half2 s2 = __hadd2(__hadd2(*(const __half2*)&t0v.z,
                                           *(const __half2*)&t1v.z),
                                   *(const __half2*)&t2v.z);
        const __half2 s3 = __hadd2(__hadd2(*(const __half2*)&t0v.w,
                                           *(const __half2*)&t1v.w),
                                   *(const __half2*)&t2v.w);

        const float2 h0 = __half22float2(s0);
        const float2 h1 = __half22float2(s1);
        const float2 h2 = __half22float2(s2);
        const float2 h3 = __half22float2(s3);

        const float2 c0 = __half22float2(*(const __half2*)&cv.x);
        const float2 c1 = __half22float2(*(const __half2*)&cv.y);
        const float2 c2 = __half22float2(*(const __half2*)&cv.z);
        const float2 c3 = __half22float2(*(const __half2*)&cv.w);

        float4 oA, oB;
        oA.x = fmaxf(fmaf(fmaf(h0.x, rs, nmrs), gA.x, bA.x), 0.0f) + c0.x;
        oA.y = fmaxf(fmaf(fmaf(h0.y, rs, nmrs), gA.y, bA.y), 0.0f) + c0.y;
        oA.z = fmaxf(fmaf(fmaf(h1.x, rs, nmrs), gA.z, bA.z), 0.0f) + c1.x;
        oA.w = fmaxf(fmaf(fmaf(h1.y, rs, nmrs), gA.w, bA.w), 0.0f) + c1.y;
        oB.x = fmaxf(fmaf(fmaf(h2.x, rs, nmrs), gB.x, bB.x), 0.0f) + c2.x;
        oB.y = fmaxf(fmaf(fmaf(h2.y, rs, nmrs), gB.y, bB.y), 0.0f) + c2.y;
        oB.z = fmaxf(fmaf(fmaf(h3.x, rs, nmrs), gB.z, bB.z), 0.0f) + c3.x;
        oB.w = fmaxf(fmaf(fmaf(h3.y, rs, nmrs), gB.w, bB.w), 0.0f) + c3.y;

        if (!(mc >> 31)) {
            oA.x = oA.y = oA.z = oA.w = 0.0f;
            oB.x = oB.y = oB.z = oB.w = 0.0f;
        }

        stg_cs32(out + oofs, oA, oB);
        oofs += OSTEP;
    }
}

extern "C" void kernel_launch(void* const* d_in, const int* in_sizes, int n_in,
                              void* d_out, int out_size)
{
    const int*   token_ids = (const int*)  d_in[0];
    const int*   actors    = (const int*)  d_in[1];
    const int*   streets   = (const int*)  d_in[2];
    const float* masks     = (const float*)d_in[3];
    const float* actor_w   = (const float*)d_in[4];
    const float* street_w  = (const float*)d_in[5];
    const float* pos_w     = (const float*)d_in[6];
    const float* mlp_w     = (const float*)d_in[7];
    const float* mlp_b     = (const float*)d_in[8];
    const float* ln_g      = (const float*)d_in[9];
    const float* ln_b      = (const float*)d_in[10];
    float*       out       = (float*)d_out;

    precompute1<<<NB_META + NB_SQD + NB_TBL + NB_COMBO, 256>>>(
        mlp_w, mlp_b, actor_w, street_w, pos_w,
        token_ids, actors, streets, masks);
    precompute3<<<256, 256>>>();
    action_emb_kernel<<<NBLOCKS, THREADS>>>(ln_g, ln_b, out);
}